// round 3
// baseline (speedup 1.0000x reference)
#include <cuda_runtime.h>
#include <cuda_bf16.h>
#include <cstdint>

// Problem constants
#define BATCH 2
#define SEQ   2048
#define HID   1024
#define NH    16
#define HD    64
#define MROWS (BATCH * SEQ)   // 4096

// ---------------- scratch (device globals; no allocation allowed) -------
__device__ float g_h[MROWS * HID];
__device__ float g_q[MROWS * HID];
__device__ float g_k[MROWS * HID];
__device__ float g_v[MROWS * HID];
__device__ float g_ctx[MROWS * HID];
__device__ float g_wq[HID * HID];
__device__ float g_wk[HID * HID];
__device__ float g_wv[HID * HID];
__device__ float g_wd[HID * HID];

// ======================= helpers ========================================
__device__ __forceinline__ uint32_t smem_u32(const void* p) {
    uint32_t a;
    asm("{ .reg .u64 t; cvta.to.shared.u64 t, %1; cvt.u32.u64 %0, t; }"
        : "=r"(a) : "l"(p));
    return a;
}
__device__ __forceinline__ float tf32r(float x) {
    float y;
    asm("cvt.rna.tf32.f32 %0, %1;" : "=f"(y) : "f"(x));
    return y;
}
#define CP_ASYNC16(dst, src) \
    asm volatile("cp.async.cg.shared.global [%0], [%1], 16;" \
                 :: "r"(dst), "l"(src) : "memory")
#define CP_COMMIT() asm volatile("cp.async.commit_group;" ::: "memory")
#define CP_WAIT2()  asm volatile("cp.async.wait_group 2;" ::: "memory")

__device__ __forceinline__ void mma_tf32(float& c0, float& c1, float& c2, float& c3,
                                         uint32_t a0, uint32_t a1, uint32_t a2, uint32_t a3,
                                         uint32_t b0, uint32_t b1) {
    asm volatile("mma.sync.aligned.m16n8k8.row.col.f32.tf32.tf32.f32 "
                 "{%0,%1,%2,%3}, {%4,%5,%6,%7}, {%8,%9}, {%0,%1,%2,%3};"
                 : "+f"(c0), "+f"(c1), "+f"(c2), "+f"(c3)
                 : "r"(a0), "r"(a1), "r"(a2), "r"(a3), "r"(b0), "r"(b1));
}

// ---------------- weight pre-round to tf32 ------------------------------
__global__ void __launch_bounds__(256) round_kernel(const float* __restrict__ W,
                                                    float* __restrict__ O) {
    int i = blockIdx.x * 256 + threadIdx.x;   // float4 index
    float4 v = ((const float4*)W)[i];
    v.x = tf32r(v.x); v.y = tf32r(v.y); v.z = tf32r(v.z); v.w = tf32r(v.w);
    ((float4*)O)[i] = v;
}

// ---------------- LayerNorm (tf32-rounded output) -----------------------
__global__ void __launch_bounds__(256) ln_kernel(const float* __restrict__ X,
                                                 const float* __restrict__ gamma,
                                                 const float* __restrict__ beta,
                                                 float* __restrict__ Y) {
    int row = blockIdx.x;
    const float4* xr = (const float4*)(X + (size_t)row * HID);
    float4 v = xr[threadIdx.x];
    float s  = v.x + v.y + v.z + v.w;
    float ss = v.x*v.x + v.y*v.y + v.z*v.z + v.w*v.w;

    #pragma unroll
    for (int off = 16; off; off >>= 1) {
        s  += __shfl_xor_sync(0xffffffffu, s,  off);
        ss += __shfl_xor_sync(0xffffffffu, ss, off);
    }
    __shared__ float rs[8], rss[8];
    int w = threadIdx.x >> 5, ln = threadIdx.x & 31;
    if (ln == 0) { rs[w] = s; rss[w] = ss; }
    __syncthreads();
    float ts = 0.f, tss = 0.f;
    #pragma unroll
    for (int i = 0; i < 8; i++) { ts += rs[i]; tss += rss[i]; }
    float mu  = ts * (1.0f / HID);
    float var = tss * (1.0f / HID) - mu * mu;
    float inv = rsqrtf(var + 1e-12f);

    float4 g  = ((const float4*)gamma)[threadIdx.x];
    float4 be = ((const float4*)beta)[threadIdx.x];
    float4 r;
    r.x = tf32r((v.x - mu) * inv * g.x + be.x);
    r.y = tf32r((v.y - mu) * inv * g.y + be.y);
    r.z = tf32r((v.z - mu) * inv * g.z + be.z);
    r.w = tf32r((v.w - mu) * inv * g.w + be.w);
    ((float4*)(Y + (size_t)row * HID))[threadIdx.x] = r;
}

// ================= tf32 mma.sync GEMM:  C = A @ B^T + bias ==============
// A: [M,K] row-major (tf32-rounded), B: [N,K] row-major (tf32-rounded).
#define GKS 32                         // K floats per stage
#define GSTAGE_B (128 * GKS * 4)       // 16 KB per operand per stage
#define GEMM_SMEM (3 * 2 * GSTAGE_B)   // 98304 B

// smem float index for (row, k) within one 128x32 tile, XOR-swizzled 16B units
__device__ __forceinline__ uint32_t swz(int row, int k) {
    return (uint32_t)(row * GKS + ((((k >> 2) ^ row) & 7) << 2) + (k & 3));
}

__device__ __forceinline__ void issue_stage(const float* __restrict__ Ab,
                                            const float* __restrict__ Bb,
                                            int K, int k0,
                                            uint32_t sA, uint32_t sB, int tid) {
    #pragma unroll
    for (int i = 0; i < 4; i++) {
        int id  = tid + (i << 8);       // 0..1023
        int row = id >> 3;
        int c   = id & 7;               // 16B unit within row
        uint32_t dst = (uint32_t)(((row << 3) + (c ^ (row & 7))) << 4);
        CP_ASYNC16(sA + dst, Ab + (size_t)row * K + k0 + (c << 2));
        CP_ASYNC16(sB + dst, Bb + (size_t)row * K + k0 + (c << 2));
    }
}

__global__ void __launch_bounds__(256, 2) gemm_tc(const float* __restrict__ A,
                                                  const float* __restrict__ B,
                                                  const float* __restrict__ bias,
                                                  float* __restrict__ C,
                                                  int M, int N, int K) {
    extern __shared__ float smg[];
    uint32_t sb = smem_u32(smg);
    int tid = threadIdx.x;
    int wid = tid >> 5;
    int lane = tid & 31;
    int lq = lane >> 2;      // group id 0..7
    int lc = lane & 3;       // thread-in-group 0..3
    int wm = wid & 1;        // warp row (64 M each)
    int wn = wid >> 1;       // warp col (32 N each)
    int m0 = blockIdx.y * 128, n0 = blockIdx.x * 128;
    const float* Ab = A + (size_t)m0 * K;
    const float* Bb = B + (size_t)n0 * K;

    float c[4][4][4];
    #pragma unroll
    for (int i = 0; i < 4; i++)
        #pragma unroll
        for (int j = 0; j < 4; j++) {
            c[i][j][0] = 0.f; c[i][j][1] = 0.f;
            c[i][j][2] = 0.f; c[i][j][3] = 0.f;
        }

    const int nst = K / GKS;   // 32
    // prologue: stages 0..2
    #pragma unroll
    for (int s = 0; s < 3; s++) {
        issue_stage(Ab, Bb, K, s * GKS, sb + s * 2 * GSTAGE_B,
                    sb + s * 2 * GSTAGE_B + GSTAGE_B, tid);
        CP_COMMIT();
    }

    for (int s = 0; s < nst; s++) {
        CP_WAIT2();
        __syncthreads();
        int buf = s % 3;
        const float* As = smg + buf * 2 * (GSTAGE_B / 4);
        const float* Bs = As + GSTAGE_B / 4;

        #pragma unroll
        for (int k8 = 0; k8 < 4; k8++) {
            int kb = k8 * 8 + 2 * lc;   // phys k pair (kb, kb+1)
            uint32_t afr[4][4];
            #pragma unroll
            for (int mt = 0; mt < 4; mt++) {
                int r0 = wm * 64 + mt * 16 + lq;
                float2 v0 = *(const float2*)&As[swz(r0,     kb)];
                float2 v1 = *(const float2*)&As[swz(r0 + 8, kb)];
                afr[mt][0] = __float_as_uint(v0.x);
                afr[mt][1] = __float_as_uint(v1.x);
                afr[mt][2] = __float_as_uint(v0.y);
                afr[mt][3] = __float_as_uint(v1.y);
            }
            uint32_t bfr[4][2];
            #pragma unroll
            for (int nt = 0; nt < 4; nt++) {
                int nr = wn * 32 + nt * 8 + lq;
                float2 v = *(const float2*)&Bs[swz(nr, kb)];
                bfr[nt][0] = __float_as_uint(v.x);
                bfr[nt][1] = __float_as_uint(v.y);
            }
            #pragma unroll
            for (int mt = 0; mt < 4; mt++)
                #pragma unroll
                for (int nt = 0; nt < 4; nt++)
                    mma_tf32(c[mt][nt][0], c[mt][nt][1], c[mt][nt][2], c[mt][nt][3],
                             afr[mt][0], afr[mt][1], afr[mt][2], afr[mt][3],
                             bfr[nt][0], bfr[nt][1]);
        }
        __syncthreads();
        if (s + 3 < nst)
            issue_stage(Ab, Bb, K, (s + 3) * GKS, sb + buf * 2 * GSTAGE_B,
                        sb + buf * 2 * GSTAGE_B + GSTAGE_B, tid);
        CP_COMMIT();   // uniform group count (empty in tail)
    }

    // epilogue
    #pragma unroll
    for (int mt = 0; mt < 4; mt++) {
        #pragma unroll
        for (int nt = 0; nt < 4; nt++) {
            int row = m0 + wm * 64 + mt * 16 + lq;
            int col = n0 + wn * 32 + nt * 8 + 2 * lc;
            float b0 = bias[col], b1 = bias[col + 1];
            float2 r0 = make_float2(c[mt][nt][0] + b0, c[mt][nt][1] + b1);
            float2 r1 = make_float2(c[mt][nt][2] + b0, c[mt][nt][3] + b1);
            *(float2*)&C[(size_t)row * N + col]       = r0;
            *(float2*)&C[(size_t)(row + 8) * N + col] = r1;
        }
    }
}

// ---------------- Flash attention (fp32, ctx tf32-rounded) --------------
#define QT 128
#define KT 64
#define QSTR 132
#define KSTR 68
#define ATTN_SMEM_FLOATS (HD * QSTR + KT * QSTR + KT * KSTR + KT)
#define ATTN_SMEM_BYTES (ATTN_SMEM_FLOATS * 4)

__global__ void __launch_bounds__(256) attn_kernel(const float* __restrict__ Q,
                                                   const float* __restrict__ K,
                                                   const float* __restrict__ V,
                                                   const float* __restrict__ amask,
                                                   float* __restrict__ O) {
    extern __shared__ float sm[];
    float* Qst = sm;
    float* KPs = Qst + HD * QSTR;
    float* Vs  = KPs + KT * QSTR;
    float* msk = Vs + KT * KSTR;

    int b = blockIdx.z, hh = blockIdx.y;
    int q0 = blockIdx.x * QT;
    int tid = threadIdx.x;
    int tx = tid & 15, ty = tid >> 4;

    size_t rowbase = ((size_t)b * SEQ) * HID + hh * HD;

    for (int idx = tid; idx < QT * HD; idx += 256) {
        int s = idx >> 6, d = idx & 63;
        Qst[d * QSTR + s] = Q[rowbase + (size_t)(q0 + s) * HID + d];
    }

    float m_i[8], l_i[8], o[8][4];
    #pragma unroll
    for (int i = 0; i < 8; i++) {
        m_i[i] = -1e30f; l_i[i] = 0.f;
        #pragma unroll
        for (int dd = 0; dd < 4; dd++) o[i][dd] = 0.f;
    }

    for (int kk = 0; kk < SEQ; kk += KT) {
        __syncthreads();
        for (int idx = tid; idx < KT * HD; idx += 256) {
            int s = idx >> 6, d = idx & 63;
            size_t g = rowbase + (size_t)(kk + s) * HID + d;
            KPs[d * KSTR + s] = K[g];
            Vs[s * KSTR + d]  = V[g];
        }
        if (tid < KT) msk[tid] = -1000.0f * (1.0f - amask[b * SEQ + kk + tid]);
        __syncthreads();

        float sreg[8][4];
        #pragma unroll
        for (int i = 0; i < 8; i++)
            #pragma unroll
            for (int j = 0; j < 4; j++) sreg[i][j] = 0.f;

        #pragma unroll 4
        for (int d = 0; d < HD; d++) {
            float4 a0 = *(float4*)&Qst[d * QSTR + ty * 8];
            float4 a1 = *(float4*)&Qst[d * QSTR + ty * 8 + 4];
            float4 bq = *(float4*)&KPs[d * KSTR + tx * 4];
            float a[8] = {a0.x, a0.y, a0.z, a0.w, a1.x, a1.y, a1.z, a1.w};
            float bb[4] = {bq.x, bq.y, bq.z, bq.w};
            #pragma unroll
            for (int i = 0; i < 8; i++)
                #pragma unroll
                for (int j = 0; j < 4; j++) sreg[i][j] += a[i] * bb[j];
        }
        float mk[4];
        #pragma unroll
        for (int j = 0; j < 4; j++) mk[j] = msk[tx * 4 + j];

        __syncthreads();

        #pragma unroll
        for (int i = 0; i < 8; i++) {
            float mt = -1e30f;
            #pragma unroll
            for (int j = 0; j < 4; j++) {
                sreg[i][j] = sreg[i][j] * 0.125f + mk[j];
                mt = fmaxf(mt, sreg[i][j]);
            }
            #pragma unroll
            for (int off = 8; off; off >>= 1)
                mt = fmaxf(mt, __shfl_xor_sync(0xffffffffu, mt, off));
            float mn = fmaxf(m_i[i], mt);
            float lt = 0.f;
            #pragma unroll
            for (int j = 0; j < 4; j++) {
                float p = __expf(sreg[i][j] - mn);
                sreg[i][j] = p;
                lt += p;
            }
            #pragma unroll
            for (int off = 8; off; off >>= 1)
                lt += __shfl_xor_sync(0xffffffffu, lt, off);
            float sc = __expf(m_i[i] - mn);
            l_i[i] = l_i[i] * sc + lt;
            m_i[i] = mn;
            #pragma unroll
            for (int dd = 0; dd < 4; dd++) o[i][dd] *= sc;
            #pragma unroll
            for (int j = 0; j < 4; j++)
                KPs[(tx * 4 + j) * QSTR + ty * 8 + i] = sreg[i][j];
        }
        __syncthreads();

        #pragma unroll 4
        for (int kr = 0; kr < KT; kr++) {
            float4 p0 = *(float4*)&KPs[kr * QSTR + ty * 8];
            float4 p1 = *(float4*)&KPs[kr * QSTR + ty * 8 + 4];
            float4 vv = *(float4*)&Vs[kr * KSTR + tx * 4];
            float pq[8] = {p0.x, p0.y, p0.z, p0.w, p1.x, p1.y, p1.z, p1.w};
            float vb[4] = {vv.x, vv.y, vv.z, vv.w};
            #pragma unroll
            for (int i = 0; i < 8; i++)
                #pragma unroll
                for (int dd = 0; dd < 4; dd++) o[i][dd] += pq[i] * vb[dd];
        }
    }

    #pragma unroll
    for (int i = 0; i < 8; i++) {
        float inv = 1.0f / l_i[i];
        int s = q0 + ty * 8 + i;
        float4 r;
        r.x = tf32r(o[i][0] * inv); r.y = tf32r(o[i][1] * inv);
        r.z = tf32r(o[i][2] * inv); r.w = tf32r(o[i][3] * inv);
        *(float4*)&O[rowbase + (size_t)s * HID + tx * 4] = r;
    }
}

// ---------------- launch -------------------------------------------------
extern "C" void kernel_launch(void* const* d_in, const int* in_sizes, int n_in,
                              void* d_out, int out_size) {
    const float* hs    = (const float*)d_in[0];
    const float* amask = (const float*)d_in[1];
    const float* Wq    = (const float*)d_in[2];
    const float* bq    = (const float*)d_in[3];
    const float* Wk    = (const float*)d_in[4];
    const float* bk    = (const float*)d_in[5];
    const float* Wv    = (const float*)d_in[6];
    const float* bv    = (const float*)d_in[7];
    const float* Wd    = (const float*)d_in[8];
    const float* bd    = (const float*)d_in[9];
    const float* gamma = (const float*)d_in[10];
    const float* beta  = (const float*)d_in[11];
    float* out = (float*)d_out;

    float *h, *q, *k, *v, *ctx, *wq, *wk, *wv, *wd;
    cudaGetSymbolAddress((void**)&h,   g_h);
    cudaGetSymbolAddress((void**)&q,   g_q);
    cudaGetSymbolAddress((void**)&k,   g_k);
    cudaGetSymbolAddress((void**)&v,   g_v);
    cudaGetSymbolAddress((void**)&ctx, g_ctx);
    cudaGetSymbolAddress((void**)&wq,  g_wq);
    cudaGetSymbolAddress((void**)&wk,  g_wk);
    cudaGetSymbolAddress((void**)&wv,  g_wv);
    cudaGetSymbolAddress((void**)&wd,  g_wd);

    const int rblocks = (HID * HID / 4) / 256;   // 1024
    round_kernel<<<rblocks, 256>>>(Wq, wq);
    round_kernel<<<rblocks, 256>>>(Wk, wk);
    round_kernel<<<rblocks, 256>>>(Wv, wv);
    round_kernel<<<rblocks, 256>>>(Wd, wd);

    ln_kernel<<<MROWS, 256>>>(hs, gamma, beta, h);

    cudaFuncSetAttribute(gemm_tc, cudaFuncAttributeMaxDynamicSharedMemorySize,
                         GEMM_SMEM);
    dim3 ggrid(HID / 128, MROWS / 128);   // (8, 32)
    gemm_tc<<<ggrid, 256, GEMM_SMEM>>>(h, wq, bq, q, MROWS, HID, HID);
    gemm_tc<<<ggrid, 256, GEMM_SMEM>>>(h, wk, bk, k, MROWS, HID, HID);
    gemm_tc<<<ggrid, 256, GEMM_SMEM>>>(h, wv, bv, v, MROWS, HID, HID);

    cudaFuncSetAttribute(attn_kernel, cudaFuncAttributeMaxDynamicSharedMemorySize,
                         ATTN_SMEM_BYTES);
    dim3 agrid(SEQ / QT, NH, BATCH);    // (16, 16, 2)
    attn_kernel<<<agrid, 256, ATTN_SMEM_BYTES>>>(q, k, v, amask, ctx);

    gemm_tc<<<ggrid, 256, GEMM_SMEM>>>(ctx, wd, bd, out, MROWS, HID, HID);
}

// round 4
// speedup vs baseline: 1.1108x; 1.1108x over previous
#include <cuda_runtime.h>
#include <cuda_bf16.h>
#include <cstdint>

// Problem constants
#define BATCH 2
#define SEQ   2048
#define HID   1024
#define NH    16
#define HD    64
#define MROWS (BATCH * SEQ)   // 4096

// ---------------- scratch (device globals; no allocation allowed) -------
__device__ float g_h[MROWS * HID];
__device__ float g_q[MROWS * HID];
__device__ float g_k[MROWS * HID];
__device__ float g_v[MROWS * HID];
__device__ float g_ctx[MROWS * HID];

// ---------------- LayerNorm --------------------------------------------
__global__ void __launch_bounds__(256) ln_kernel(const float* __restrict__ X,
                                                 const float* __restrict__ gamma,
                                                 const float* __restrict__ beta,
                                                 float* __restrict__ Y) {
    int row = blockIdx.x;
    const float4* xr = (const float4*)(X + (size_t)row * HID);
    float4 v = xr[threadIdx.x];
    float s  = v.x + v.y + v.z + v.w;
    float ss = v.x*v.x + v.y*v.y + v.z*v.z + v.w*v.w;

    #pragma unroll
    for (int off = 16; off; off >>= 1) {
        s  += __shfl_xor_sync(0xffffffffu, s,  off);
        ss += __shfl_xor_sync(0xffffffffu, ss, off);
    }
    __shared__ float rs[8], rss[8];
    int w = threadIdx.x >> 5, ln = threadIdx.x & 31;
    if (ln == 0) { rs[w] = s; rss[w] = ss; }
    __syncthreads();
    float ts = 0.f, tss = 0.f;
    #pragma unroll
    for (int i = 0; i < 8; i++) { ts += rs[i]; tss += rss[i]; }
    float mu  = ts * (1.0f / HID);
    float var = tss * (1.0f / HID) - mu * mu;
    float inv = rsqrtf(var + 1e-12f);

    float4 g  = ((const float4*)gamma)[threadIdx.x];
    float4 be = ((const float4*)beta)[threadIdx.x];
    float4 r;
    r.x = (v.x - mu) * inv * g.x + be.x;
    r.y = (v.y - mu) * inv * g.y + be.y;
    r.z = (v.z - mu) * inv * g.z + be.z;
    r.w = (v.w - mu) * inv * g.w + be.w;
    ((float4*)(Y + (size_t)row * HID))[threadIdx.x] = r;
}

// ========== SGEMM (double-buffered):  C = A @ B^T + bias ================
// A: [M,K] row-major, B: [N,K] row-major.
#define BM 128
#define BN 128
#define BKG 16
#define SPAD 132
#define TILE_F (BKG * SPAD)   // 2112 floats per operand tile

__global__ void __launch_bounds__(256, 2) sgemm_db(const float* __restrict__ A,
                                                   const float* __restrict__ B,
                                                   const float* __restrict__ bias,
                                                   float* __restrict__ C,
                                                   int M, int N, int K) {
    __shared__ float sm[4 * TILE_F];   // A0, B0, A1, B1  (33.8 KB)
    int m0 = blockIdx.y * BM, n0 = blockIdx.x * BN;
    int tid = threadIdx.x;
    int tx = tid & 15, ty = tid >> 4;

    const float* Ab = A + (size_t)m0 * K;
    const float* Bb = B + (size_t)n0 * K;

    float c[8][8];
    #pragma unroll
    for (int i = 0; i < 8; i++)
        #pragma unroll
        for (int j = 0; j < 8; j++) c[i][j] = 0.f;

    float4 ra[2], rb[2];
    // id decomposition (shared by ldg/sts): id in 0..511 -> row 0..127, kq in {0,4,8,12}
    #define G_LDG(k0) do { \
        _Pragma("unroll") \
        for (int i = 0; i < 2; i++) { \
            int id = tid + (i << 8); \
            int row = id >> 2, kq = (id & 3) << 2; \
            ra[i] = *(const float4*)&Ab[(size_t)row * K + (k0) + kq]; \
            rb[i] = *(const float4*)&Bb[(size_t)row * K + (k0) + kq]; \
        } } while (0)
    #define G_STS(buf) do { \
        float* As_ = sm + (buf) * 2 * TILE_F; \
        float* Bs_ = As_ + TILE_F; \
        _Pragma("unroll") \
        for (int i = 0; i < 2; i++) { \
            int id = tid + (i << 8); \
            int row = id >> 2, kq = (id & 3) << 2; \
            As_[(kq + 0) * SPAD + row] = ra[i].x; \
            As_[(kq + 1) * SPAD + row] = ra[i].y; \
            As_[(kq + 2) * SPAD + row] = ra[i].z; \
            As_[(kq + 3) * SPAD + row] = ra[i].w; \
            Bs_[(kq + 0) * SPAD + row] = rb[i].x; \
            Bs_[(kq + 1) * SPAD + row] = rb[i].y; \
            Bs_[(kq + 2) * SPAD + row] = rb[i].z; \
            Bs_[(kq + 3) * SPAD + row] = rb[i].w; \
        } } while (0)

    G_LDG(0);
    G_STS(0);
    __syncthreads();

    const int nst = K / BKG;
    for (int it = 0; it < nst; it++) {
        int buf = it & 1;
        bool more = (it + 1) < nst;
        if (more) G_LDG((it + 1) * BKG);

        const float* As = sm + buf * 2 * TILE_F;
        const float* Bs = As + TILE_F;
        #pragma unroll
        for (int k = 0; k < BKG; k++) {
            float4 a0 = *(const float4*)&As[k * SPAD + ty * 8];
            float4 a1 = *(const float4*)&As[k * SPAD + ty * 8 + 4];
            float4 b0 = *(const float4*)&Bs[k * SPAD + tx * 8];
            float4 b1 = *(const float4*)&Bs[k * SPAD + tx * 8 + 4];
            float a[8] = {a0.x, a0.y, a0.z, a0.w, a1.x, a1.y, a1.z, a1.w};
            float bb[8] = {b0.x, b0.y, b0.z, b0.w, b1.x, b1.y, b1.z, b1.w};
            #pragma unroll
            for (int i = 0; i < 8; i++)
                #pragma unroll
                for (int j = 0; j < 8; j++) c[i][j] += a[i] * bb[j];
        }
        if (more) {
            G_STS(buf ^ 1);
            __syncthreads();
        }
    }

    float4 bi0 = *(const float4*)&bias[n0 + tx * 8];
    float4 bi1 = *(const float4*)&bias[n0 + tx * 8 + 4];
    #pragma unroll
    for (int i = 0; i < 8; i++) {
        int row = m0 + ty * 8 + i;
        float4 r0, r1;
        r0.x = c[i][0] + bi0.x; r0.y = c[i][1] + bi0.y;
        r0.z = c[i][2] + bi0.z; r0.w = c[i][3] + bi0.w;
        r1.x = c[i][4] + bi1.x; r1.y = c[i][5] + bi1.y;
        r1.z = c[i][6] + bi1.z; r1.w = c[i][7] + bi1.w;
        *(float4*)&C[(size_t)row * N + n0 + tx * 8]     = r0;
        *(float4*)&C[(size_t)row * N + n0 + tx * 8 + 4] = r1;
    }
    #undef G_LDG
    #undef G_STS
}

// ---------------- Flash attention (fp32, K/V register prefetch) ---------
#define QT 128
#define KT 64
#define QSTR 132
#define KSTR 68
#define ATTN_SMEM_FLOATS (HD * QSTR + KT * QSTR + KT * KSTR + KT)
#define ATTN_SMEM_BYTES (ATTN_SMEM_FLOATS * 4)

__global__ void __launch_bounds__(256) attn_kernel(const float* __restrict__ Q,
                                                   const float* __restrict__ K,
                                                   const float* __restrict__ V,
                                                   const float* __restrict__ amask,
                                                   float* __restrict__ O) {
    extern __shared__ float sm[];
    float* Qst = sm;                      // [HD][QSTR]
    float* KPs = Qst + HD * QSTR;         // union: Kst [HD][KSTR] / P [KT][QSTR]
    float* Vs  = KPs + KT * QSTR;         // [KT][KSTR]
    float* msk = Vs + KT * KSTR;          // [KT]

    int b = blockIdx.z, hh = blockIdx.y;
    int q0 = blockIdx.x * QT;
    int tid = threadIdx.x;
    int tx = tid & 15, ty = tid >> 4;
    int sld = tid >> 4;        // s-row this thread loads (0..15 per j-step)
    int d4  = (tid & 15) * 4;  // d-quad this thread loads

    size_t rowbase = ((size_t)b * SEQ) * HID + hh * HD;

    float4 kreg[4], vreg[4];
    #define KV_LDG(kk) do { \
        _Pragma("unroll") \
        for (int j = 0; j < 4; j++) { \
            int s = sld + j * 16; \
            size_t g = rowbase + (size_t)((kk) + s) * HID + d4; \
            kreg[j] = *(const float4*)&K[g]; \
            vreg[j] = *(const float4*)&V[g]; \
        } } while (0)
    #define KV_STS(kk) do { \
        _Pragma("unroll") \
        for (int j = 0; j < 4; j++) { \
            int s = sld + j * 16; \
            KPs[(d4 + 0) * KSTR + s] = kreg[j].x; \
            KPs[(d4 + 1) * KSTR + s] = kreg[j].y; \
            KPs[(d4 + 2) * KSTR + s] = kreg[j].z; \
            KPs[(d4 + 3) * KSTR + s] = kreg[j].w; \
            *(float4*)&Vs[s * KSTR + d4] = vreg[j]; \
        } \
        if (tid < KT) msk[tid] = -1000.0f * (1.0f - amask[b * SEQ + (kk) + tid]); \
        } while (0)

    // preload Q tile (transposed) + tile 0 of K/V
    for (int idx = tid; idx < QT * HD; idx += 256) {
        int s = idx >> 6, d = idx & 63;
        Qst[d * QSTR + s] = Q[rowbase + (size_t)(q0 + s) * HID + d];
    }
    KV_LDG(0);
    KV_STS(0);
    __syncthreads();

    float m_i[8], l_i[8], o[8][4];
    #pragma unroll
    for (int i = 0; i < 8; i++) {
        m_i[i] = -1e30f; l_i[i] = 0.f;
        #pragma unroll
        for (int dd = 0; dd < 4; dd++) o[i][dd] = 0.f;
    }

    for (int kk = 0; kk < SEQ; kk += KT) {
        bool more = (kk + KT) < SEQ;
        if (more) KV_LDG(kk + KT);   // long-latency loads overlap everything below

        // S = (Q K^T) * 0.125 + mask
        float sreg[8][4];
        #pragma unroll
        for (int i = 0; i < 8; i++)
            #pragma unroll
            for (int j = 0; j < 4; j++) sreg[i][j] = 0.f;

        #pragma unroll 4
        for (int d = 0; d < HD; d++) {
            float4 a0 = *(float4*)&Qst[d * QSTR + ty * 8];
            float4 a1 = *(float4*)&Qst[d * QSTR + ty * 8 + 4];
            float4 bq = *(float4*)&KPs[d * KSTR + tx * 4];
            float a[8] = {a0.x, a0.y, a0.z, a0.w, a1.x, a1.y, a1.z, a1.w};
            float bb[4] = {bq.x, bq.y, bq.z, bq.w};
            #pragma unroll
            for (int i = 0; i < 8; i++)
                #pragma unroll
                for (int j = 0; j < 4; j++) sreg[i][j] += a[i] * bb[j];
        }
        float mk[4];
        #pragma unroll
        for (int j = 0; j < 4; j++) mk[j] = msk[tx * 4 + j];

        __syncthreads();   // K reads done; KPs region may become P

        #pragma unroll
        for (int i = 0; i < 8; i++) {
            float mt = -1e30f;
            #pragma unroll
            for (int j = 0; j < 4; j++) {
                sreg[i][j] = sreg[i][j] * 0.125f + mk[j];
                mt = fmaxf(mt, sreg[i][j]);
            }
            #pragma unroll
            for (int off = 8; off; off >>= 1)
                mt = fmaxf(mt, __shfl_xor_sync(0xffffffffu, mt, off));
            float mn = fmaxf(m_i[i], mt);
            float lt = 0.f;
            #pragma unroll
            for (int j = 0; j < 4; j++) {
                float p = __expf(sreg[i][j] - mn);
                sreg[i][j] = p;
                lt += p;
            }
            #pragma unroll
            for (int off = 8; off; off >>= 1)
                lt += __shfl_xor_sync(0xffffffffu, lt, off);
            float sc = __expf(m_i[i] - mn);
            l_i[i] = l_i[i] * sc + lt;
            m_i[i] = mn;
            #pragma unroll
            for (int dd = 0; dd < 4; dd++) o[i][dd] *= sc;
            #pragma unroll
            for (int j = 0; j < 4; j++)
                KPs[(tx * 4 + j) * QSTR + ty * 8 + i] = sreg[i][j];
        }
        __syncthreads();   // P visible

        // O += P @ V
        #pragma unroll 4
        for (int kr = 0; kr < KT; kr++) {
            float4 p0 = *(float4*)&KPs[kr * QSTR + ty * 8];
            float4 p1 = *(float4*)&KPs[kr * QSTR + ty * 8 + 4];
            float4 vv = *(float4*)&Vs[kr * KSTR + tx * 4];
            float pq[8] = {p0.x, p0.y, p0.z, p0.w, p1.x, p1.y, p1.z, p1.w};
            float vb[4] = {vv.x, vv.y, vv.z, vv.w};
            #pragma unroll
            for (int i = 0; i < 8; i++)
                #pragma unroll
                for (int dd = 0; dd < 4; dd++) o[i][dd] += pq[i] * vb[dd];
        }

        if (more) {
            __syncthreads();   // PV done; safe to overwrite K/V/msk
            KV_STS(kk + KT);
            __syncthreads();
        }
    }

    #pragma unroll
    for (int i = 0; i < 8; i++) {
        float inv = 1.0f / l_i[i];
        int s = q0 + ty * 8 + i;
        float4 r;
        r.x = o[i][0] * inv; r.y = o[i][1] * inv;
        r.z = o[i][2] * inv; r.w = o[i][3] * inv;
        *(float4*)&O[rowbase + (size_t)s * HID + tx * 4] = r;
    }
    #undef KV_LDG
    #undef KV_STS
}

// ---------------- launch -------------------------------------------------
extern "C" void kernel_launch(void* const* d_in, const int* in_sizes, int n_in,
                              void* d_out, int out_size) {
    const float* hs    = (const float*)d_in[0];
    const float* amask = (const float*)d_in[1];
    const float* Wq    = (const float*)d_in[2];
    const float* bq    = (const float*)d_in[3];
    const float* Wk    = (const float*)d_in[4];
    const float* bk    = (const float*)d_in[5];
    const float* Wv    = (const float*)d_in[6];
    const float* bv    = (const float*)d_in[7];
    const float* Wd    = (const float*)d_in[8];
    const float* bd    = (const float*)d_in[9];
    const float* gamma = (const float*)d_in[10];
    const float* beta  = (const float*)d_in[11];
    float* out = (float*)d_out;

    float *h, *q, *k, *v, *ctx;
    cudaGetSymbolAddress((void**)&h,   g_h);
    cudaGetSymbolAddress((void**)&q,   g_q);
    cudaGetSymbolAddress((void**)&k,   g_k);
    cudaGetSymbolAddress((void**)&v,   g_v);
    cudaGetSymbolAddress((void**)&ctx, g_ctx);

    ln_kernel<<<MROWS, 256>>>(hs, gamma, beta, h);

    dim3 ggrid(HID / BN, MROWS / BM);   // (8, 32)
    sgemm_db<<<ggrid, 256>>>(h, Wq, bq, q, MROWS, HID, HID);
    sgemm_db<<<ggrid, 256>>>(h, Wk, bk, k, MROWS, HID, HID);
    sgemm_db<<<ggrid, 256>>>(h, Wv, bv, v, MROWS, HID, HID);

    cudaFuncSetAttribute(attn_kernel, cudaFuncAttributeMaxDynamicSharedMemorySize,
                         ATTN_SMEM_BYTES);
    dim3 agrid(SEQ / QT, NH, BATCH);    // (16, 16, 2)
    attn_kernel<<<agrid, 256, ATTN_SMEM_BYTES>>>(q, k, v, amask, ctx);

    sgemm_db<<<ggrid, 256>>>(ctx, Wd, bd, out, MROWS, HID, HID);
}